// round 15
// baseline (speedup 1.0000x reference)
#include <cuda_runtime.h>
#include <cuda_bf16.h>
#include <cuda_fp16.h>
#include <math.h>

// Problem constants (with headroom on N/E for safety)
#define FIN   500
#define FH    128
#define FOUT  47
#define NMAX  65536
#define EMAX  1048576

// ---------------- scratch (static device globals; no allocation) -------------
__device__ __align__(16) float g_dinv[NMAX];
__device__ int   g_cnt[NMAX];
__device__ int   g_rowptr[NMAX];
__device__ int   g_wp[NMAX];
__device__ int   g_col[EMAX];
__device__ int   g_total;
__device__ __align__(16) unsigned g_H1bf [(size_t)NMAX * 64];  // x @ W1, bf16x2
__device__ __align__(16) unsigned g_H2bf [(size_t)NMAX * 32];  // H1r @ W2, bf16x2, 64-col pad
__device__ __align__(16) unsigned g_W2bf [128 * 32];           // W2 bf16x2, 64-col pad
__device__ int   g_is64;

__device__ __forceinline__ int ld_edge(const int* p, long long idx, int is64) {
    return is64 ? p[2 * idx] : p[idx];
}
__device__ __forceinline__ unsigned pack_bf16(float a, float b) {
    return ((unsigned)__bfloat16_as_ushort(__float2bfloat16(b)) << 16) |
           __bfloat16_as_ushort(__float2bfloat16(a));
}

// ---------------- init: zero counters + dtype detect + W2 pack ---------------
// int64 LE: odd 32-bit words are 0 (values < 50000). int32: odd words random.
__global__ void k_init(const int* ei, const float* W2, int n) {
    int i = blockIdx.x * blockDim.x + threadIdx.x;
    if (i < n) g_cnt[i] = 0;
    if (blockIdx.x == 0 && threadIdx.x < 32) {
        int lane = threadIdx.x;
        int nz = (ei[2 * lane + 1] != 0) ? 1 : 0;
        unsigned b = __ballot_sync(0xffffffffu, nz);
        if (lane == 0) { g_is64 = (b == 0u) ? 1 : 0; g_total = 0; }
    }
    if (blockIdx.x == 1) {
        for (int idx = threadIdx.x; idx < 128 * 32; idx += blockDim.x) {
            int k = idx >> 5, c2 = idx & 31;
            float f0 = (2 * c2     < FOUT) ? W2[k * FOUT + 2 * c2]     : 0.f;
            float f1 = (2 * c2 + 1 < FOUT) ? W2[k * FOUT + 2 * c2 + 1] : 0.f;
            g_W2bf[idx] = pack_bf16(f0, f1);
        }
    }
}

__global__ void k_degree(const int* ei, long long E) {
    long long e = (long long)blockIdx.x * blockDim.x + threadIdx.x;
    if (e >= E) return;
    int is64 = g_is64;
    int dst = ld_edge(ei, E + e, is64);
    atomicAdd(&g_cnt[dst], 1);
}

// ---------------- k_alloc: atomic chunk allocation (order-free CSR) ----------
__global__ void k_alloc(int n) {
    __shared__ int sh[256];
    __shared__ int base_sh;
    int t = threadIdx.x;
    int i = blockIdx.x * 256 + t;
    int c = (i < n) ? g_cnt[i] : 0;
    sh[t] = c;
    __syncthreads();
#pragma unroll
    for (int off = 1; off < 256; off <<= 1) {
        int u = (t >= off) ? sh[t - off] : 0;
        __syncthreads();
        sh[t] += u;
        __syncthreads();
    }
    if (t == 0) base_sh = atomicAdd(&g_total, sh[255]);
    __syncthreads();
    if (i < n) {
        int pos = base_sh + sh[t] - c;
        g_rowptr[i] = pos;
        g_wp[i] = pos;
        g_dinv[i] = rsqrtf((float)(c + 1));   // +1 self-loop
    }
}

__global__ void k_scatter(const int* ei, long long E) {
    long long e = (long long)blockIdx.x * blockDim.x + threadIdx.x;
    if (e >= E) return;
    int is64 = g_is64;
    int src = ld_edge(ei, e, is64);
    int dst = ld_edge(ei, E + e, is64);
    int pos = atomicAdd(&g_wp[dst], 1);
    g_col[pos] = src;
}

// ---------------- mma helpers ------------------------------------------------
__device__ __forceinline__ void ldsm_x4(unsigned& r0, unsigned& r1, unsigned& r2, unsigned& r3,
                                        unsigned addr) {
    asm volatile("ldmatrix.sync.aligned.m8n8.x4.shared.b16 {%0,%1,%2,%3}, [%4];\n"
                 : "=r"(r0), "=r"(r1), "=r"(r2), "=r"(r3) : "r"(addr));
}
__device__ __forceinline__ void ldsm_x4_t(unsigned& r0, unsigned& r1, unsigned& r2, unsigned& r3,
                                          unsigned addr) {
    asm volatile("ldmatrix.sync.aligned.m8n8.x4.trans.shared.b16 {%0,%1,%2,%3}, [%4];\n"
                 : "=r"(r0), "=r"(r1), "=r"(r2), "=r"(r3) : "r"(addr));
}
__device__ __forceinline__ void mma_fp16(float* d, const unsigned* a, const unsigned* b) {
    asm volatile("mma.sync.aligned.m16n8k16.row.col.f32.f16.f16.f32 "
                 "{%0,%1,%2,%3}, {%4,%5,%6,%7}, {%8,%9}, {%0,%1,%2,%3};\n"
                 : "+f"(d[0]), "+f"(d[1]), "+f"(d[2]), "+f"(d[3])
                 : "r"(a[0]), "r"(a[1]), "r"(a[2]), "r"(a[3]), "r"(b[0]), "r"(b[1]));
}
__device__ __forceinline__ void mma_bf16(float* d, const unsigned* a, const unsigned* b) {
    asm volatile("mma.sync.aligned.m16n8k16.row.col.f32.bf16.bf16.f32 "
                 "{%0,%1,%2,%3}, {%4,%5,%6,%7}, {%8,%9}, {%0,%1,%2,%3};\n"
                 : "+f"(d[0]), "+f"(d[1]), "+f"(d[2]), "+f"(d[3])
                 : "r"(a[0]), "r"(a[1]), "r"(a[2]), "r"(a[3]), "r"(b[0]), "r"(b[1]));
}
// float4 -> 2x packed half2
__device__ __forceinline__ uint2 cvt4h(const float4 v) {
    __half2 h0 = __floats2half2_rn(v.x, v.y);
    __half2 h1 = __floats2half2_rn(v.z, v.w);
    uint2 r;
    r.x = *reinterpret_cast<unsigned*>(&h0);
    r.y = *reinterpret_cast<unsigned*>(&h1);
    return r;
}

// ---------------- GEMM1: H1 = x @ W1 via fp16 tensor cores -------------------
// 128x128 block tile, BK=16, K padded to 512 (32 chunks). 8 warps = 4m x 2n.
#define G1_KT 32
#define A_LDS 24
#define B_LDS 136
__global__ __launch_bounds__(256) void k_gemm1(
    const float* __restrict__ x, const float* __restrict__ W, int n)
{
    __shared__ __align__(16) __half As[2][128][A_LDS];
    __shared__ __align__(16) __half Bs[2][16][B_LDS];

    int tid = threadIdx.x;
    int lane = tid & 31;
    int wid = tid >> 5;
    int wm = wid & 3;
    int wn = wid >> 2;
    int row0 = blockIdx.x * 128;

    float acc[2][8][4];
#pragma unroll
    for (int mi = 0; mi < 2; mi++)
#pragma unroll
        for (int ni = 0; ni < 8; ni++)
#pragma unroll
            for (int q = 0; q < 4; q++) acc[mi][ni][q] = 0.f;

    unsigned a_base = (unsigned)__cvta_generic_to_shared(&As[0][0][0]);
    unsigned b_base = (unsigned)__cvta_generic_to_shared(&Bs[0][0][0]);
    const unsigned A_BUF = 128 * A_LDS * 2;
    const unsigned B_BUF = 16 * B_LDS * 2;
    unsigned a_lane = ((lane & 15) * A_LDS + (lane >> 4) * 8) * 2;
    unsigned b_lane = ((lane & 15) * B_LDS + (lane >> 4) * 8) * 2;

    float4 a_ld[2], b_ld[2];

#define G1_LOAD(k0)                                                            \
    {                                                                          \
        _Pragma("unroll")                                                      \
        for (int u = 0; u < 2; u++) {                                          \
            int f4 = tid + u * 256;                                            \
            int a_row = f4 >> 2, grp = f4 & 3;                                 \
            int gk = (k0) + grp * 4;                                           \
            int gr = row0 + a_row;                                             \
            if (gr < n && gk + 4 <= FIN)                                       \
                a_ld[u] = *reinterpret_cast<const float4*>(&x[(size_t)gr * FIN + gk]); \
            else a_ld[u] = make_float4(0.f, 0.f, 0.f, 0.f);                    \
            int bk = f4 >> 5, bc4 = f4 & 31;                                   \
            int gkb = (k0) + bk;                                               \
            if (gkb < FIN)                                                     \
                b_ld[u] = *reinterpret_cast<const float4*>(&W[(size_t)gkb * FH + bc4 * 4]); \
            else b_ld[u] = make_float4(0.f, 0.f, 0.f, 0.f);                    \
        }                                                                      \
    }

#define G1_STORE(buf)                                                          \
    {                                                                          \
        _Pragma("unroll")                                                      \
        for (int u = 0; u < 2; u++) {                                          \
            int f4 = tid + u * 256;                                            \
            int a_row = f4 >> 2, grp = f4 & 3;                                 \
            *reinterpret_cast<uint2*>(&As[buf][a_row][grp * 4]) = cvt4h(a_ld[u]); \
            int bk = f4 >> 5, bc4 = f4 & 31;                                   \
            *reinterpret_cast<uint2*>(&Bs[buf][bk][bc4 * 4]) = cvt4h(b_ld[u]); \
        }                                                                      \
    }

    G1_LOAD(0)
    G1_STORE(0)
    __syncthreads();

    for (int kt = 0; kt < G1_KT; kt++) {
        int cbuf = kt & 1;
        if (kt + 1 < G1_KT) G1_LOAD((kt + 1) * 16)

        unsigned af[2][4], bfr[8][2];
#pragma unroll
        for (int mi = 0; mi < 2; mi++) {
            unsigned roff = (unsigned)((wm * 32 + mi * 16) * A_LDS * 2);
            ldsm_x4(af[mi][0], af[mi][1], af[mi][2], af[mi][3],
                    a_base + cbuf * A_BUF + roff + a_lane);
        }
#pragma unroll
        for (int p = 0; p < 4; p++) {
            unsigned coff = (unsigned)((wn * 64 + p * 16) * 2);
            ldsm_x4_t(bfr[2*p][0], bfr[2*p][1], bfr[2*p+1][0], bfr[2*p+1][1],
                      b_base + cbuf * B_BUF + coff + b_lane);
        }

#pragma unroll
        for (int mi = 0; mi < 2; mi++)
#pragma unroll
            for (int ni = 0; ni < 8; ni++)
                mma_fp16(acc[mi][ni], af[mi], bfr[ni]);

        if (kt + 1 < G1_KT) G1_STORE(cbuf ^ 1)
        __syncthreads();
    }

    int rbase = row0 + wm * 32 + (lane >> 2);
    int cbase = wn * 64 + (lane & 3) * 2;
#pragma unroll
    for (int mi = 0; mi < 2; mi++) {
#pragma unroll
        for (int ni = 0; ni < 8; ni++) {
            int col = cbase + ni * 8;      // even
            int r0 = rbase + mi * 16;
            if (r0 < n)
                g_H1bf[(size_t)r0 * 64 + (col >> 1)] =
                    pack_bf16(acc[mi][ni][0], acc[mi][ni][1]);
            if (r0 + 8 < n)
                g_H1bf[(size_t)(r0 + 8) * 64 + (col >> 1)] =
                    pack_bf16(acc[mi][ni][2], acc[mi][ni][3]);
        }
    }
#undef G1_LOAD
#undef G1_STORE
}

// ---------------- fused agg1 + gemm2 -----------------------------------------
// Block = 64 nodes. Phase 1: warp w aggregates nodes w*8..w*8+7 (gather bf16
// H1 rows, relu+bias) directly into smem As (bf16, ldmatrix layout).
// Phase 2: 64x64 bf16 MMA tile H2 = As @ W2, output packed bf16 to g_H2bf.
#define G2_ALD 136   // bf16 per A row (128 + 8 pad)
#define G2_BLD 72    // bf16 per B row (64 + 8 pad)
__device__ __forceinline__ void bf2_fma(float4& acc, uint2 u, float w) {
    float f0 = __uint_as_float(u.x << 16);
    float f1 = __uint_as_float(u.x & 0xffff0000u);
    float f2 = __uint_as_float(u.y << 16);
    float f3 = __uint_as_float(u.y & 0xffff0000u);
    acc.x += f0 * w; acc.y += f1 * w; acc.z += f2 * w; acc.w += f3 * w;
}
__global__ __launch_bounds__(256) void k_agg1g2(const float* __restrict__ b1, int n) {
    __shared__ __align__(16) __nv_bfloat16 As[64][G2_ALD];
    __shared__ __align__(16) __nv_bfloat16 Bs[128][G2_BLD];

    int tid = threadIdx.x;
    int lane = tid & 31;
    int wid = tid >> 5;
    int row0 = blockIdx.x * 64;

    // W2 -> Bs (independent of aggregation)
    const uint4* Wb = reinterpret_cast<const uint4*>(g_W2bf);
#pragma unroll
    for (int u = 0; u < 4; u++) {
        int f = tid + u * 256;
        int k = f >> 3, seg = f & 7;
        *reinterpret_cast<uint4*>(&Bs[k][seg * 8]) = Wb[f];
    }

    // Phase 1: aggregation. Warp wid handles 8 nodes.
    const uint2* H = reinterpret_cast<const uint2*>(g_H1bf);
    float4 bias = reinterpret_cast<const float4*>(b1)[lane];
    for (int t = 0; t < 8; t++) {
        int i = row0 + wid * 8 + t;
        if (i < n) {
            float di = g_dinv[i];
            float4 acc = make_float4(0.f, 0.f, 0.f, 0.f);
            bf2_fma(acc, H[(size_t)i * 32 + lane], di * di);   // self loop
            int beg = g_rowptr[i], end = beg + g_cnt[i];
            for (int base = beg; base < end; base += 32) {
                int c = end - base; if (c > 32) c = 32;
                int s = 0; float w = 0.f;
                if (lane < c) { s = g_col[base + lane]; w = g_dinv[s] * di; }
                int k = 0;
                for (; k + 8 <= c; k += 8) {
                    int si[8]; float wi[8]; uint2 vi[8];
#pragma unroll
                    for (int q = 0; q < 8; q++) {
                        si[q] = __shfl_sync(0xffffffffu, s, k + q);
                        wi[q] = __shfl_sync(0xffffffffu, w, k + q);
                    }
#pragma unroll
                    for (int q = 0; q < 8; q++)
                        vi[q] = H[(size_t)si[q] * 32 + lane];
#pragma unroll
                    for (int q = 0; q < 8; q++)
                        bf2_fma(acc, vi[q], wi[q]);
                }
                for (; k < c; k++) {
                    int   sk = __shfl_sync(0xffffffffu, s, k);
                    float wk = __shfl_sync(0xffffffffu, w, k);
                    bf2_fma(acc, H[(size_t)sk * 32 + lane], wk);
                }
            }
            uint2 o;
            o.x = pack_bf16(fmaxf(acc.x + bias.x, 0.f), fmaxf(acc.y + bias.y, 0.f));
            o.y = pack_bf16(fmaxf(acc.z + bias.z, 0.f), fmaxf(acc.w + bias.w, 0.f));
            int r = wid * 8 + t;
            *reinterpret_cast<uint2*>(&As[r][lane * 4]) = o;
        }
    }
    __syncthreads();

    // Phase 2: 64x64 bf16 MMA. 8 warps = 2m x 4n.
    int wm = wid & 1;    // 2 warps along m, 32 rows each
    int wn = wid >> 1;   // 4 warps along n, 16 cols each

    float acc[2][2][4];
#pragma unroll
    for (int mi = 0; mi < 2; mi++)
#pragma unroll
        for (int ni = 0; ni < 2; ni++)
#pragma unroll
            for (int q = 0; q < 4; q++) acc[mi][ni][q] = 0.f;

    unsigned a_base = (unsigned)__cvta_generic_to_shared(&As[0][0]);
    unsigned b_base = (unsigned)__cvta_generic_to_shared(&Bs[0][0]);

#pragma unroll
    for (int k = 0; k < 8; k++) {
        unsigned af[2][4], bfr[2][2];
#pragma unroll
        for (int mi = 0; mi < 2; mi++) {
            unsigned addr = a_base +
                (unsigned)(((wm * 32 + mi * 16 + (lane & 15)) * G2_ALD +
                            k * 16 + (lane >> 4) * 8) * 2);
            ldsm_x4(af[mi][0], af[mi][1], af[mi][2], af[mi][3], addr);
        }
        unsigned baddr = b_base +
            (unsigned)(((k * 16 + (lane & 15)) * G2_BLD +
                        wn * 16 + (lane >> 4) * 8) * 2);
        ldsm_x4_t(bfr[0][0], bfr[0][1], bfr[1][0], bfr[1][1], baddr);
#pragma unroll
        for (int mi = 0; mi < 2; mi++)
#pragma unroll
            for (int ni = 0; ni < 2; ni++)
                mma_bf16(acc[mi][ni], af[mi], bfr[ni]);
    }

    int r_ = wm * 32 + (lane >> 2);
    int c0 = wn * 16 + (lane & 3) * 2;   // even
#pragma unroll
    for (int mi = 0; mi < 2; mi++) {
#pragma unroll
        for (int ni = 0; ni < 2; ni++) {
            int row = row0 + r_ + mi * 16;
            int col = c0 + ni * 8;
            if (row < n)
                g_H2bf[(size_t)row * 32 + (col >> 1)] =
                    pack_bf16(acc[mi][ni][0], acc[mi][ni][1]);
            if (row + 8 < n)
                g_H2bf[(size_t)(row + 8) * 32 + (col >> 1)] =
                    pack_bf16(acc[mi][ni][2], acc[mi][ni][3]);
        }
    }
}

// ---------------- agg2 + bias + log_softmax (bf16 gathers) -------------------
__global__ __launch_bounds__(256) void k_agg2(
    const float* __restrict__ b2, float* __restrict__ out, int n)
{
    int gw = (blockIdx.x * blockDim.x + threadIdx.x) >> 5;
    int lane = threadIdx.x & 31;
    if (gw >= n) return;
    int i = gw;
    float di = g_dinv[i];
    float sw = di * di;
    const unsigned* H = g_H2bf;
    unsigned u0 = H[(size_t)i * 32 + lane];
    float ax = __uint_as_float(u0 << 16) * sw;
    float ay = __uint_as_float(u0 & 0xffff0000u) * sw;

    int beg = g_rowptr[i], end = beg + g_cnt[i];
    for (int base = beg; base < end; base += 32) {
        int c = end - base; if (c > 32) c = 32;
        int s = 0; float w = 0.f;
        if (lane < c) { s = g_col[base + lane]; w = g_dinv[s] * di; }
        int k = 0;
        for (; k + 8 <= c; k += 8) {
            int si[8]; float wi[8]; unsigned vi[8];
#pragma unroll
            for (int q = 0; q < 8; q++) {
                si[q] = __shfl_sync(0xffffffffu, s, k + q);
                wi[q] = __shfl_sync(0xffffffffu, w, k + q);
            }
#pragma unroll
            for (int q = 0; q < 8; q++)
                vi[q] = H[(size_t)si[q] * 32 + lane];
#pragma unroll
            for (int q = 0; q < 8; q++) {
                ax += __uint_as_float(vi[q] << 16) * wi[q];
                ay += __uint_as_float(vi[q] & 0xffff0000u) * wi[q];
            }
        }
        for (; k < c; k++) {
            int   sk = __shfl_sync(0xffffffffu, s, k);
            float wk = __shfl_sync(0xffffffffu, w, k);
            unsigned v = H[(size_t)sk * 32 + lane];
            ax += __uint_as_float(v << 16) * wk;
            ay += __uint_as_float(v & 0xffff0000u) * wk;
        }
    }

    int f0 = 2 * lane, f1 = 2 * lane + 1;
    bool v0 = f0 < FOUT, v1 = f1 < FOUT;
    if (v0) ax += b2[f0];
    if (v1) ay += b2[f1];

    float m = fmaxf(v0 ? ax : -INFINITY, v1 ? ay : -INFINITY);
#pragma unroll
    for (int off = 16; off; off >>= 1) m = fmaxf(m, __shfl_xor_sync(0xffffffffu, m, off));
    float e = (v0 ? expf(ax - m) : 0.f) + (v1 ? expf(ay - m) : 0.f);
#pragma unroll
    for (int off = 16; off; off >>= 1) e += __shfl_xor_sync(0xffffffffu, e, off);
    float ls = m + logf(e);
    if (v0) out[(size_t)i * FOUT + f0] = ax - ls;
    if (v1) out[(size_t)i * FOUT + f1] = ay - ls;
}

// ---------------- launch ----------------------------------------------------
// CSR build (stream 0) runs concurrently with gemm1 (stream s1); disjoint
// buffers. Fork/join via events (captured into the graph). Stream/event
// handles are host-side resources created once.
extern "C" void kernel_launch(void* const* d_in, const int* in_sizes, int n_in,
                              void* d_out, int out_size)
{
    const float* x  = (const float*)d_in[0];
    const float* W1 = (const float*)d_in[1];
    const float* b1 = (const float*)d_in[2];
    const float* W2 = (const float*)d_in[3];
    const float* b2 = (const float*)d_in[4];
    const int*   ei = (const int*)d_in[5];   // int32 or int64; detected on device
    float* out = (float*)d_out;

    int n = in_sizes[0] / FIN;
    long long E = in_sizes[5] / 2;
    int nb = (n + 255) / 256;

    static cudaStream_t s1 = nullptr;
    static cudaEvent_t eFork = nullptr, eJoin = nullptr;
    if (s1 == nullptr) {
        cudaStreamCreateWithFlags(&s1, cudaStreamNonBlocking);
        cudaEventCreateWithFlags(&eFork, cudaEventDisableTiming);
        cudaEventCreateWithFlags(&eJoin, cudaEventDisableTiming);
    }

    // fork: gemm1 on s1, independent of the CSR build
    cudaEventRecord(eFork, 0);
    cudaStreamWaitEvent(s1, eFork, 0);
    k_gemm1<<<(n + 127) / 128, 256, 0, s1>>>(x, W1, n);
    cudaEventRecord(eJoin, s1);

    // CSR build on stream 0
    k_init<<<nb, 256>>>(ei, W2, n);
    k_degree<<<(int)((E + 255) / 256), 256>>>(ei, E);
    k_alloc<<<nb, 256>>>(n);
    k_scatter<<<(int)((E + 255) / 256), 256>>>(ei, E);

    // join: fused agg1+gemm2 needs both CSR and H1
    cudaStreamWaitEvent(0, eJoin, 0);
    k_agg1g2<<<(n + 63) / 64, 256>>>(b1, n);
    k_agg2<<<(n * 32 + 255) / 256, 256>>>(b2, out, n);
}

// round 17
// speedup vs baseline: 1.0463x; 1.0463x over previous
#include <cuda_runtime.h>
#include <cuda_bf16.h>
#include <cuda_fp16.h>
#include <math.h>

// Problem constants (with headroom on N/E for safety)
#define FIN   500
#define FH    128
#define FOUT  47
#define NMAX  65536
#define EMAX  1048576

// ---------------- scratch (static device globals; no allocation) -------------
__device__ __align__(16) float g_dinv[NMAX];
__device__ int   g_cnt[NMAX];
__device__ int   g_rowptr[NMAX];
__device__ int   g_wp[NMAX];
__device__ int   g_col[EMAX];
__device__ int   g_total;
__device__ __align__(16) unsigned g_H1bf [(size_t)NMAX * 64];  // x @ W1, bf16x2
__device__ __align__(16) unsigned g_H1rbf[(size_t)NMAX * 64];  // relu(agg1+b1), bf16x2
__device__ __align__(16) unsigned g_H2bf [(size_t)NMAX * 32];  // H1r @ W2, bf16x2, 64-col pad
__device__ __align__(16) unsigned g_W2bf [128 * 32];           // W2 bf16x2, 64-col pad
__device__ int   g_is64;

__device__ __forceinline__ int ld_edge(const int* p, long long idx, int is64) {
    return is64 ? p[2 * idx] : p[idx];
}
__device__ __forceinline__ unsigned pack_bf16(float a, float b) {
    return ((unsigned)__bfloat16_as_ushort(__float2bfloat16(b)) << 16) |
           __bfloat16_as_ushort(__float2bfloat16(a));
}

// ---------------- init: zero counters + dtype detect + W2 pack ---------------
// int64 LE: odd 32-bit words are 0 (values < 50000). int32: odd words random.
__global__ void k_init(const int* ei, const float* W2, int n) {
    int i = blockIdx.x * blockDim.x + threadIdx.x;
    if (i < n) g_cnt[i] = 0;
    if (blockIdx.x == 0 && threadIdx.x < 32) {
        int lane = threadIdx.x;
        int nz = (ei[2 * lane + 1] != 0) ? 1 : 0;
        unsigned b = __ballot_sync(0xffffffffu, nz);
        if (lane == 0) { g_is64 = (b == 0u) ? 1 : 0; g_total = 0; }
    }
    if (blockIdx.x == 1) {
        for (int idx = threadIdx.x; idx < 128 * 32; idx += blockDim.x) {
            int k = idx >> 5, c2 = idx & 31;
            float f0 = (2 * c2     < FOUT) ? W2[k * FOUT + 2 * c2]     : 0.f;
            float f1 = (2 * c2 + 1 < FOUT) ? W2[k * FOUT + 2 * c2 + 1] : 0.f;
            g_W2bf[idx] = pack_bf16(f0, f1);
        }
    }
}

__global__ void k_degree(const int* ei, long long E) {
    long long e = (long long)blockIdx.x * blockDim.x + threadIdx.x;
    if (e >= E) return;
    int is64 = g_is64;
    int dst = ld_edge(ei, E + e, is64);
    atomicAdd(&g_cnt[dst], 1);
}

// ---------------- k_alloc: atomic chunk allocation (order-free CSR) ----------
__global__ void k_alloc(int n) {
    __shared__ int sh[256];
    __shared__ int base_sh;
    int t = threadIdx.x;
    int i = blockIdx.x * 256 + t;
    int c = (i < n) ? g_cnt[i] : 0;
    sh[t] = c;
    __syncthreads();
#pragma unroll
    for (int off = 1; off < 256; off <<= 1) {
        int u = (t >= off) ? sh[t - off] : 0;
        __syncthreads();
        sh[t] += u;
        __syncthreads();
    }
    if (t == 0) base_sh = atomicAdd(&g_total, sh[255]);
    __syncthreads();
    if (i < n) {
        int pos = base_sh + sh[t] - c;
        g_rowptr[i] = pos;
        g_wp[i] = pos;
        g_dinv[i] = rsqrtf((float)(c + 1));   // +1 self-loop
    }
}

__global__ void k_scatter(const int* ei, long long E) {
    long long e = (long long)blockIdx.x * blockDim.x + threadIdx.x;
    if (e >= E) return;
    int is64 = g_is64;
    int src = ld_edge(ei, e, is64);
    int dst = ld_edge(ei, E + e, is64);
    int pos = atomicAdd(&g_wp[dst], 1);
    g_col[pos] = src;
}

// ---------------- mma helpers ------------------------------------------------
__device__ __forceinline__ void ldsm_x4(unsigned& r0, unsigned& r1, unsigned& r2, unsigned& r3,
                                        unsigned addr) {
    asm volatile("ldmatrix.sync.aligned.m8n8.x4.shared.b16 {%0,%1,%2,%3}, [%4];\n"
                 : "=r"(r0), "=r"(r1), "=r"(r2), "=r"(r3) : "r"(addr));
}
__device__ __forceinline__ void ldsm_x4_t(unsigned& r0, unsigned& r1, unsigned& r2, unsigned& r3,
                                          unsigned addr) {
    asm volatile("ldmatrix.sync.aligned.m8n8.x4.trans.shared.b16 {%0,%1,%2,%3}, [%4];\n"
                 : "=r"(r0), "=r"(r1), "=r"(r2), "=r"(r3) : "r"(addr));
}
__device__ __forceinline__ void mma_fp16(float* d, const unsigned* a, const unsigned* b) {
    asm volatile("mma.sync.aligned.m16n8k16.row.col.f32.f16.f16.f32 "
                 "{%0,%1,%2,%3}, {%4,%5,%6,%7}, {%8,%9}, {%0,%1,%2,%3};\n"
                 : "+f"(d[0]), "+f"(d[1]), "+f"(d[2]), "+f"(d[3])
                 : "r"(a[0]), "r"(a[1]), "r"(a[2]), "r"(a[3]), "r"(b[0]), "r"(b[1]));
}
__device__ __forceinline__ void mma_bf16(float* d, const unsigned* a, const unsigned* b) {
    asm volatile("mma.sync.aligned.m16n8k16.row.col.f32.bf16.bf16.f32 "
                 "{%0,%1,%2,%3}, {%4,%5,%6,%7}, {%8,%9}, {%0,%1,%2,%3};\n"
                 : "+f"(d[0]), "+f"(d[1]), "+f"(d[2]), "+f"(d[3])
                 : "r"(a[0]), "r"(a[1]), "r"(a[2]), "r"(a[3]), "r"(b[0]), "r"(b[1]));
}
// float4 -> 2x packed half2
__device__ __forceinline__ uint2 cvt4h(const float4 v) {
    __half2 h0 = __floats2half2_rn(v.x, v.y);
    __half2 h1 = __floats2half2_rn(v.z, v.w);
    uint2 r;
    r.x = *reinterpret_cast<unsigned*>(&h0);
    r.y = *reinterpret_cast<unsigned*>(&h1);
    return r;
}

// ---------------- GEMM1: H1 = x @ W1 via fp16 tensor cores -------------------
// 128x128 block tile, BK=16, K padded to 512 (32 chunks). 8 warps = 4m x 2n.
#define G1_KT 32
#define A_LDS 24
#define B_LDS 136
__global__ __launch_bounds__(256) void k_gemm1(
    const float* __restrict__ x, const float* __restrict__ W, int n)
{
    __shared__ __align__(16) __half As[2][128][A_LDS];
    __shared__ __align__(16) __half Bs[2][16][B_LDS];

    int tid = threadIdx.x;
    int lane = tid & 31;
    int wid = tid >> 5;
    int wm = wid & 3;
    int wn = wid >> 2;
    int row0 = blockIdx.x * 128;

    float acc[2][8][4];
#pragma unroll
    for (int mi = 0; mi < 2; mi++)
#pragma unroll
        for (int ni = 0; ni < 8; ni++)
#pragma unroll
            for (int q = 0; q < 4; q++) acc[mi][ni][q] = 0.f;

    unsigned a_base = (unsigned)__cvta_generic_to_shared(&As[0][0][0]);
    unsigned b_base = (unsigned)__cvta_generic_to_shared(&Bs[0][0][0]);
    const unsigned A_BUF = 128 * A_LDS * 2;
    const unsigned B_BUF = 16 * B_LDS * 2;
    unsigned a_lane = ((lane & 15) * A_LDS + (lane >> 4) * 8) * 2;
    unsigned b_lane = ((lane & 15) * B_LDS + (lane >> 4) * 8) * 2;

    float4 a_ld[2], b_ld[2];

#define G1_LOAD(k0)                                                            \
    {                                                                          \
        _Pragma("unroll")                                                      \
        for (int u = 0; u < 2; u++) {                                          \
            int f4 = tid + u * 256;                                            \
            int a_row = f4 >> 2, grp = f4 & 3;                                 \
            int gk = (k0) + grp * 4;                                           \
            int gr = row0 + a_row;                                             \
            if (gr < n && gk + 4 <= FIN)                                       \
                a_ld[u] = *reinterpret_cast<const float4*>(&x[(size_t)gr * FIN + gk]); \
            else a_ld[u] = make_float4(0.f, 0.f, 0.f, 0.f);                    \
            int bk = f4 >> 5, bc4 = f4 & 31;                                   \
            int gkb = (k0) + bk;                                               \
            if (gkb < FIN)                                                     \
                b_ld[u] = *reinterpret_cast<const float4*>(&W[(size_t)gkb * FH + bc4 * 4]); \
            else b_ld[u] = make_float4(0.f, 0.f, 0.f, 0.f);                    \
        }                                                                      \
    }

#define G1_STORE(buf)                                                          \
    {                                                                          \
        _Pragma("unroll")                                                      \
        for (int u = 0; u < 2; u++) {                                          \
            int f4 = tid + u * 256;                                            \
            int a_row = f4 >> 2, grp = f4 & 3;                                 \
            *reinterpret_cast<uint2*>(&As[buf][a_row][grp * 4]) = cvt4h(a_ld[u]); \
            int bk = f4 >> 5, bc4 = f4 & 31;                                   \
            *reinterpret_cast<uint2*>(&Bs[buf][bk][bc4 * 4]) = cvt4h(b_ld[u]); \
        }                                                                      \
    }

    G1_LOAD(0)
    G1_STORE(0)
    __syncthreads();

    for (int kt = 0; kt < G1_KT; kt++) {
        int cbuf = kt & 1;
        if (kt + 1 < G1_KT) G1_LOAD((kt + 1) * 16)

        unsigned af[2][4], bfr[8][2];
#pragma unroll
        for (int mi = 0; mi < 2; mi++) {
            unsigned roff = (unsigned)((wm * 32 + mi * 16) * A_LDS * 2);
            ldsm_x4(af[mi][0], af[mi][1], af[mi][2], af[mi][3],
                    a_base + cbuf * A_BUF + roff + a_lane);
        }
#pragma unroll
        for (int p = 0; p < 4; p++) {
            unsigned coff = (unsigned)((wn * 64 + p * 16) * 2);
            ldsm_x4_t(bfr[2*p][0], bfr[2*p][1], bfr[2*p+1][0], bfr[2*p+1][1],
                      b_base + cbuf * B_BUF + coff + b_lane);
        }

#pragma unroll
        for (int mi = 0; mi < 2; mi++)
#pragma unroll
            for (int ni = 0; ni < 8; ni++)
                mma_fp16(acc[mi][ni], af[mi], bfr[ni]);

        if (kt + 1 < G1_KT) G1_STORE(cbuf ^ 1)
        __syncthreads();
    }

    int rbase = row0 + wm * 32 + (lane >> 2);
    int cbase = wn * 64 + (lane & 3) * 2;
#pragma unroll
    for (int mi = 0; mi < 2; mi++) {
#pragma unroll
        for (int ni = 0; ni < 8; ni++) {
            int col = cbase + ni * 8;      // even
            int r0 = rbase + mi * 16;
            if (r0 < n)
                g_H1bf[(size_t)r0 * 64 + (col >> 1)] =
                    pack_bf16(acc[mi][ni][0], acc[mi][ni][1]);
            if (r0 + 8 < n)
                g_H1bf[(size_t)(r0 + 8) * 64 + (col >> 1)] =
                    pack_bf16(acc[mi][ni][2], acc[mi][ni][3]);
        }
    }
#undef G1_LOAD
#undef G1_STORE
}

// ---------------- agg1: H1r = relu( Ahat @ H1 + b1 ), bf16 out ---------------
// One warp per node (no smem); 8-wide gather unroll for MLP.
__device__ __forceinline__ void bf2_fma(float4& acc, uint2 u, float w) {
    float f0 = __uint_as_float(u.x << 16);
    float f1 = __uint_as_float(u.x & 0xffff0000u);
    float f2 = __uint_as_float(u.y << 16);
    float f3 = __uint_as_float(u.y & 0xffff0000u);
    acc.x += f0 * w; acc.y += f1 * w; acc.z += f2 * w; acc.w += f3 * w;
}
__global__ __launch_bounds__(256) void k_agg1(const float* __restrict__ b1, int n) {
    int gw = (blockIdx.x * blockDim.x + threadIdx.x) >> 5;
    int lane = threadIdx.x & 31;
    if (gw >= n) return;
    int i = gw;
    float di = g_dinv[i];
    const uint2* H = reinterpret_cast<const uint2*>(g_H1bf);
    float4 acc = make_float4(0.f, 0.f, 0.f, 0.f);
    bf2_fma(acc, H[(size_t)i * 32 + lane], di * di);   // self loop

    int beg = g_rowptr[i], end = beg + g_cnt[i];
    for (int base = beg; base < end; base += 32) {
        int c = end - base; if (c > 32) c = 32;
        int s = 0; float w = 0.f;
        if (lane < c) { s = g_col[base + lane]; w = g_dinv[s] * di; }
        int k = 0;
        for (; k + 8 <= c; k += 8) {
            int si[8]; float wi[8]; uint2 vi[8];
#pragma unroll
            for (int q = 0; q < 8; q++) {
                si[q] = __shfl_sync(0xffffffffu, s, k + q);
                wi[q] = __shfl_sync(0xffffffffu, w, k + q);
            }
#pragma unroll
            for (int q = 0; q < 8; q++)
                vi[q] = H[(size_t)si[q] * 32 + lane];
#pragma unroll
            for (int q = 0; q < 8; q++)
                bf2_fma(acc, vi[q], wi[q]);
        }
        for (; k < c; k++) {
            int   sk = __shfl_sync(0xffffffffu, s, k);
            float wk = __shfl_sync(0xffffffffu, w, k);
            bf2_fma(acc, H[(size_t)sk * 32 + lane], wk);
        }
    }
    float4 b = reinterpret_cast<const float4*>(b1)[lane];
    uint2 o;
    o.x = pack_bf16(fmaxf(acc.x + b.x, 0.f), fmaxf(acc.y + b.y, 0.f));
    o.y = pack_bf16(fmaxf(acc.z + b.z, 0.f), fmaxf(acc.w + b.w, 0.f));
    reinterpret_cast<uint2*>(g_H1rbf)[(size_t)i * 32 + lane] = o;
}

// ---------------- GEMM2: H2 = H1r @ W2 via bf16 tensor cores -----------------
// 64x64 block tile, K=128 resident in smem. 8 warps = 2m x 4n.
#define G2_ALD 136   // bf16 per A row (128 + 8 pad)
#define G2_BLD 72    // bf16 per B row (64 + 8 pad)
__global__ __launch_bounds__(256) void k_gemm2(int n) {
    __shared__ __align__(16) __nv_bfloat16 As[64][G2_ALD];
    __shared__ __align__(16) __nv_bfloat16 Bs[128][G2_BLD];

    int tid = threadIdx.x;
    int lane = tid & 31;
    int wid = tid >> 5;
    int wm = wid & 1;    // 2 warps along m, 32 rows each
    int wn = wid >> 1;   // 4 warps along n, 16 cols each
    int row0 = blockIdx.x * 64;

    const uint4* H1 = reinterpret_cast<const uint4*>(g_H1rbf);
#pragma unroll
    for (int u = 0; u < 4; u++) {
        int f = tid + u * 256;
        int r = f >> 4, seg = f & 15;
        int gr = row0 + r;
        uint4 v = make_uint4(0u, 0u, 0u, 0u);
        if (gr < n) v = H1[(size_t)gr * 16 + seg];
        *reinterpret_cast<uint4*>(&As[r][seg * 8]) = v;
    }
    const uint4* Wb = reinterpret_cast<const uint4*>(g_W2bf);
#pragma unroll
    for (int u = 0; u < 4; u++) {
        int f = tid + u * 256;
        int k = f >> 3, seg = f & 7;
        *reinterpret_cast<uint4*>(&Bs[k][seg * 8]) = Wb[f];
    }
    __syncthreads();

    float acc[2][2][4];
#pragma unroll
    for (int mi = 0; mi < 2; mi++)
#pragma unroll
        for (int ni = 0; ni < 2; ni++)
#pragma unroll
            for (int q = 0; q < 4; q++) acc[mi][ni][q] = 0.f;

    unsigned a_base = (unsigned)__cvta_generic_to_shared(&As[0][0]);
    unsigned b_base = (unsigned)__cvta_generic_to_shared(&Bs[0][0]);

#pragma unroll
    for (int k = 0; k < 8; k++) {
        unsigned af[2][4], bfr[2][2];
#pragma unroll
        for (int mi = 0; mi < 2; mi++) {
            unsigned addr = a_base +
                (unsigned)(((wm * 32 + mi * 16 + (lane & 15)) * G2_ALD +
                            k * 16 + (lane >> 4) * 8) * 2);
            ldsm_x4(af[mi][0], af[mi][1], af[mi][2], af[mi][3], addr);
        }
        unsigned baddr = b_base +
            (unsigned)(((k * 16 + (lane & 15)) * G2_BLD +
                        wn * 16 + (lane >> 4) * 8) * 2);
        ldsm_x4_t(bfr[0][0], bfr[0][1], bfr[1][0], bfr[1][1], baddr);
#pragma unroll
        for (int mi = 0; mi < 2; mi++)
#pragma unroll
            for (int ni = 0; ni < 2; ni++)
                mma_bf16(acc[mi][ni], af[mi], bfr[ni]);
    }

    int r_ = wm * 32 + (lane >> 2);
    int c0 = wn * 16 + (lane & 3) * 2;   // even
#pragma unroll
    for (int mi = 0; mi < 2; mi++) {
#pragma unroll
        for (int ni = 0; ni < 2; ni++) {
            int row = row0 + r_ + mi * 16;
            int col = c0 + ni * 8;
            if (row < n)
                g_H2bf[(size_t)row * 32 + (col >> 1)] =
                    pack_bf16(acc[mi][ni][0], acc[mi][ni][1]);
            if (row + 8 < n)
                g_H2bf[(size_t)(row + 8) * 32 + (col >> 1)] =
                    pack_bf16(acc[mi][ni][2], acc[mi][ni][3]);
        }
    }
}

// ---------------- agg2 + bias + log_softmax (bf16 gathers, 8-wide) -----------
__global__ __launch_bounds__(256) void k_agg2(
    const float* __restrict__ b2, float* __restrict__ out, int n)
{
    int gw = (blockIdx.x * blockDim.x + threadIdx.x) >> 5;
    int lane = threadIdx.x & 31;
    if (gw >= n) return;
    int i = gw;
    float di = g_dinv[i];
    float sw = di * di;
    const unsigned* H = g_H2bf;
    unsigned u0 = H[(size_t)i * 32 + lane];
    float ax = __uint_as_float(u0 << 16) * sw;
    float ay = __uint_as_float(u0 & 0xffff0000u) * sw;

    int beg = g_rowptr[i], end = beg + g_cnt[i];
    for (int base = beg; base < end; base += 32) {
        int c = end - base; if (c > 32) c = 32;
        int s = 0; float w = 0.f;
        if (lane < c) { s = g_col[base + lane]; w = g_dinv[s] * di; }
        int k = 0;
        for (; k + 8 <= c; k += 8) {
            int si[8]; float wi[8]; unsigned vi[8];
#pragma unroll
            for (int q = 0; q < 8; q++) {
                si[q] = __shfl_sync(0xffffffffu, s, k + q);
                wi[q] = __shfl_sync(0xffffffffu, w, k + q);
            }
#pragma unroll
            for (int q = 0; q < 8; q++)
                vi[q] = H[(size_t)si[q] * 32 + lane];
#pragma unroll
            for (int q = 0; q < 8; q++) {
                ax += __uint_as_float(vi[q] << 16) * wi[q];
                ay += __uint_as_float(vi[q] & 0xffff0000u) * wi[q];
            }
        }
        for (; k < c; k++) {
            int   sk = __shfl_sync(0xffffffffu, s, k);
            float wk = __shfl_sync(0xffffffffu, w, k);
            unsigned v = H[(size_t)sk * 32 + lane];
            ax += __uint_as_float(v << 16) * wk;
            ay += __uint_as_float(v & 0xffff0000u) * wk;
        }
    }

    int f0 = 2 * lane, f1 = 2 * lane + 1;
    bool v0 = f0 < FOUT, v1 = f1 < FOUT;
    if (v0) ax += b2[f0];
    if (v1) ay += b2[f1];

    float m = fmaxf(v0 ? ax : -INFINITY, v1 ? ay : -INFINITY);
#pragma unroll
    for (int off = 16; off; off >>= 1) m = fmaxf(m, __shfl_xor_sync(0xffffffffu, m, off));
    float e = (v0 ? expf(ax - m) : 0.f) + (v1 ? expf(ay - m) : 0.f);
#pragma unroll
    for (int off = 16; off; off >>= 1) e += __shfl_xor_sync(0xffffffffu, e, off);
    float ls = m + logf(e);
    if (v0) out[(size_t)i * FOUT + f0] = ax - ls;
    if (v1) out[(size_t)i * FOUT + f1] = ay - ls;
}

// ---------------- launch ----------------------------------------------------
// CSR build (stream 0) runs concurrently with gemm1 (stream s1); disjoint
// buffers. Fork/join via events (captured into the graph). Stream/event
// handles are host-side resources created once.
extern "C" void kernel_launch(void* const* d_in, const int* in_sizes, int n_in,
                              void* d_out, int out_size)
{
    const float* x  = (const float*)d_in[0];
    const float* W1 = (const float*)d_in[1];
    const float* b1 = (const float*)d_in[2];
    const float* W2 = (const float*)d_in[3];
    const float* b2 = (const float*)d_in[4];
    const int*   ei = (const int*)d_in[5];   // int32 or int64; detected on device
    float* out = (float*)d_out;

    int n = in_sizes[0] / FIN;
    long long E = in_sizes[5] / 2;
    int nb = (n + 255) / 256;

    static cudaStream_t s1 = nullptr;
    static cudaEvent_t eFork = nullptr, eJoin = nullptr;
    if (s1 == nullptr) {
        cudaStreamCreateWithFlags(&s1, cudaStreamNonBlocking);
        cudaEventCreateWithFlags(&eFork, cudaEventDisableTiming);
        cudaEventCreateWithFlags(&eJoin, cudaEventDisableTiming);
    }

    // fork: gemm1 on s1, independent of the CSR build
    cudaEventRecord(eFork, 0);
    cudaStreamWaitEvent(s1, eFork, 0);
    k_gemm1<<<(n + 127) / 128, 256, 0, s1>>>(x, W1, n);
    cudaEventRecord(eJoin, s1);

    // CSR build on stream 0
    k_init<<<nb, 256>>>(ei, W2, n);
    k_degree<<<(int)((E + 255) / 256), 256>>>(ei, E);
    k_alloc<<<nb, 256>>>(n);
    k_scatter<<<(int)((E + 255) / 256), 256>>>(ei, E);

    // join: agg1 needs both CSR and H1
    cudaStreamWaitEvent(0, eJoin, 0);
    k_agg1<<<(n * 32 + 255) / 256, 256>>>(b1, n);
    k_gemm2<<<(n + 63) / 64, 256>>>(n);
    k_agg2<<<(n * 32 + 255) / 256, 256>>>(b2, out, n);
}